// round 6
// baseline (speedup 1.0000x reference)
#include <cuda_runtime.h>
#include <cstdint>

#define INV_SQRT2 0.7071067811865476f

// x: (B=64, S=4096, F=256) fp32 contiguous -> out (B, 2048, 512):
//   out[b,s2,2f]   = (x[b,2s2,f] + x[b,2s2+1,f]) * INV_SQRT2
//   out[b,s2,2f+1] = (x[b,2s2,f] - x[b,2s2+1,f]) * INV_SQRT2
//
// Persistent single-wave grid-stride version of the 256-bit kernel.
// Work item t (t in [0, N/16)): p = t>>5, j = t&31.
//   loads  x[p*512 + 8j .. +7] and x[p*512 + 256 + 8j .. +7]   (2x LDG.256)
//   stores out[p*512 + 16j .. +15]                              (2x STG.256)
// Unroll 2 inside the loop: next iteration's loads hoist above this
// iteration's stores (independent), keeping 4 LDG.256 in flight per warp
// continuously. Register budget ~40 -> full occupancy retained.

__device__ __forceinline__ void ldg256_cs(const float* p, float* v) {
    asm volatile(
        "ld.global.cs.v8.f32 {%0,%1,%2,%3,%4,%5,%6,%7}, [%8];"
        : "=f"(v[0]), "=f"(v[1]), "=f"(v[2]), "=f"(v[3]),
          "=f"(v[4]), "=f"(v[5]), "=f"(v[6]), "=f"(v[7])
        : "l"(p));
}

__device__ __forceinline__ void stg256_cs(float* p, const float* v) {
    asm volatile(
        "st.global.cs.v8.f32 [%0], {%1,%2,%3,%4,%5,%6,%7,%8};"
        :: "l"(p),
           "f"(v[0]), "f"(v[1]), "f"(v[2]), "f"(v[3]),
           "f"(v[4]), "f"(v[5]), "f"(v[6]), "f"(v[7])
        : "memory");
}

__device__ __forceinline__ void haar_item256(const float* __restrict__ x,
                                             float* __restrict__ out,
                                             int t)
{
    int p = t >> 5;
    int j = t & 31;

    const float* x0 = x + (size_t)p * 512 + 8 * j;
    const float* x1 = x0 + 256;

    float a[8], b[8];
    ldg256_cs(x0, a);
    ldg256_cs(x1, b);

    float o[16];
    #pragma unroll
    for (int k = 0; k < 8; k++) {
        o[2 * k]     = (a[k] + b[k]) * INV_SQRT2;
        o[2 * k + 1] = (a[k] - b[k]) * INV_SQRT2;
    }

    float* op = out + (size_t)p * 512 + 16 * j;
    stg256_cs(op,     o);
    stg256_cs(op + 8, o + 8);
}

__global__ void __launch_bounds__(256) haar_kernel(const float* __restrict__ x,
                                                   float* __restrict__ out,
                                                   int total_items)
{
    const int stride = gridDim.x * blockDim.x;
    int t = blockIdx.x * blockDim.x + threadIdx.x;

    // Unroll-2 main loop: 4 LDG.256 issued before first store each round.
    for (; t + stride < total_items; t += 2 * stride) {
        haar_item256(x, out, t);
        haar_item256(x, out, t + stride);
    }
    if (t < total_items)
        haar_item256(x, out, t);
}

extern "C" void kernel_launch(void* const* d_in, const int* in_sizes, int n_in,
                              void* d_out, int out_size)
{
    const float* x = (const float*)d_in[0];
    float* out = (float*)d_out;

    int total_items = in_sizes[0] / 16;    // 16 input floats per work item

    // One persistent wave: 148 SMs x 8 CTAs x 256 threads.
    int blocks = 148 * 8;
    haar_kernel<<<blocks, 256>>>(x, out, total_items);
}

// round 7
// speedup vs baseline: 1.1205x; 1.1205x over previous
#include <cuda_runtime.h>
#include <cstdint>

#define INV_SQRT2 0.7071067811865476f

// x: (B=64, S=4096, F=256) fp32 contiguous -> out (B, 2048, 512):
//   out[b,s2,2f]   = (x[b,2s2,f] + x[b,2s2+1,f]) * INV_SQRT2
//   out[b,s2,2f+1] = (x[b,2s2,f] - x[b,2s2+1,f]) * INV_SQRT2
//
// One-shot kernel (persistence loses ~5% on this chip), store-contiguous
// mapping, adjacent unroll x2: thread (p, j) with j in [0,32) handles output
// float4 chunks {j, j+64} and {j+32, j+96} of pair p. Each warp's footprint
// is one dense 2KB-in / 2KB-out window (input row pair == output row byte
// range), maximizing DRAM row-buffer locality of concurrent requests.
// Loads: 8x lane-contiguous LDG.64.CS (MLP=8). Stores: 4x contiguous
// STG.128.CS spans of 512B each.

__device__ __forceinline__ void haar_chunk(const float2* __restrict__ x0,
                                           const float2* __restrict__ x1,
                                           float4* __restrict__ orow,
                                           int j)
{
    float2 a0 = __ldcs(x0 + j);          // f = 2j, 2j+1
    float2 b0 = __ldcs(x1 + j);
    float2 a1 = __ldcs(x0 + j + 64);     // f = 2j+128, 2j+129
    float2 b1 = __ldcs(x1 + j + 64);

    float4 o0, o1;
    o0.x = (a0.x + b0.x) * INV_SQRT2;
    o0.y = (a0.x - b0.x) * INV_SQRT2;
    o0.z = (a0.y + b0.y) * INV_SQRT2;
    o0.w = (a0.y - b0.y) * INV_SQRT2;
    o1.x = (a1.x + b1.x) * INV_SQRT2;
    o1.y = (a1.x - b1.x) * INV_SQRT2;
    o1.z = (a1.y + b1.y) * INV_SQRT2;
    o1.w = (a1.y - b1.y) * INV_SQRT2;

    __stcs(orow + j,      o0);   // output chunk j      (contiguous over warp)
    __stcs(orow + j + 64, o1);   // output chunk j+64
}

__global__ void __launch_bounds__(256) haar_kernel(const float2* __restrict__ x,
                                                   float4* __restrict__ out,
                                                   int total_threads)
{
    int tid = blockIdx.x * blockDim.x + threadIdx.x;
    if (tid >= total_threads) return;

    int p = tid >> 5;        // pair index (b*S/2 + s2)
    int j = tid & 31;        // base chunk within pair

    const float2* x0 = x + (size_t)p * 256;        // row 2s2   (as float2)
    const float2* x1 = x0 + 128;                   // row 2s2+1
    float4* orow = out + (size_t)p * 128;          // output row (as float4)

    // Two adjacent work items: chunks {j, j+64} and {j+32, j+96}.
    haar_chunk(x0, x1, orow, j);
    haar_chunk(x0, x1, orow, j + 32);
}

extern "C" void kernel_launch(void* const* d_in, const int* in_sizes, int n_in,
                              void* d_out, int out_size)
{
    const float2* x = (const float2*)d_in[0];
    float4* out = (float4*)d_out;

    // 16 input floats per thread -> threads = n / 16.
    int total_threads = in_sizes[0] / 16;

    int threads = 256;
    int blocks = (total_threads + threads - 1) / threads;
    haar_kernel<<<blocks, threads>>>(x, out, total_threads);
}

// round 11
// speedup vs baseline: 1.1240x; 1.0031x over previous
#include <cuda_runtime.h>
#include <cstdint>

#define INV_SQRT2 0.7071067811865476f

// x: (B=64, S=4096, F=256) fp32 contiguous -> out (B, 2048, 512):
//   out[b,s2,2f]   = (x[b,2s2,f] + x[b,2s2+1,f]) * INV_SQRT2
//   out[b,s2,2f+1] = (x[b,2s2,f] - x[b,2s2+1,f]) * INV_SQRT2
//
// R7 structure (one-shot, store-contiguous, adjacent unroll x2) with all 8
// streaming loads batched up-front (per-thread MLP=8, warp reads its full
// 2KB window in one burst) and 512-thread CTAs. Thread (p, j), j in [0,32):
//   reads  x0/x1 float2 chunks {j, j+32, j+64, j+96}     (8x LDG.64.CS)
//   writes output float4 chunks {j, j+32, j+64, j+96}    (4x STG.128.CS,
//          each a contiguous 512B span across the warp)

__global__ void __launch_bounds__(512) haar_kernel(const float2* __restrict__ x,
                                                   float4* __restrict__ out,
                                                   int total_threads)
{
    int tid = blockIdx.x * blockDim.x + threadIdx.x;
    if (tid >= total_threads) return;

    int p = tid >> 5;        // pair index (b*S/2 + s2)
    int j = tid & 31;        // base chunk within pair

    const float2* x0 = x + (size_t)p * 256;   // row 2s2   (float2 view)
    const float2* x1 = x0 + 128;              // row 2s2+1
    float4* orow = out + (size_t)p * 128;     // output row (float4 view)

    // ---- batched loads: 8 independent LDG.64.CS ----
    float2 a0 = __ldcs(x0 + j);
    float2 b0 = __ldcs(x1 + j);
    float2 a1 = __ldcs(x0 + j + 32);
    float2 b1 = __ldcs(x1 + j + 32);
    float2 a2 = __ldcs(x0 + j + 64);
    float2 b2 = __ldcs(x1 + j + 64);
    float2 a3 = __ldcs(x0 + j + 96);
    float2 b3 = __ldcs(x1 + j + 96);

    // ---- compute + store, in load-completion order ----
    float4 o;
    o.x = (a0.x + b0.x) * INV_SQRT2;
    o.y = (a0.x - b0.x) * INV_SQRT2;
    o.z = (a0.y + b0.y) * INV_SQRT2;
    o.w = (a0.y - b0.y) * INV_SQRT2;
    __stcs(orow + j, o);

    o.x = (a1.x + b1.x) * INV_SQRT2;
    o.y = (a1.x - b1.x) * INV_SQRT2;
    o.z = (a1.y + b1.y) * INV_SQRT2;
    o.w = (a1.y - b1.y) * INV_SQRT2;
    __stcs(orow + j + 32, o);

    o.x = (a2.x + b2.x) * INV_SQRT2;
    o.y = (a2.x - b2.x) * INV_SQRT2;
    o.z = (a2.y + b2.y) * INV_SQRT2;
    o.w = (a2.y - b2.y) * INV_SQRT2;
    __stcs(orow + j + 64, o);

    o.x = (a3.x + b3.x) * INV_SQRT2;
    o.y = (a3.x - b3.x) * INV_SQRT2;
    o.z = (a3.y + b3.y) * INV_SQRT2;
    o.w = (a3.y - b3.y) * INV_SQRT2;
    __stcs(orow + j + 96, o);
}

extern "C" void kernel_launch(void* const* d_in, const int* in_sizes, int n_in,
                              void* d_out, int out_size)
{
    const float2* x = (const float2*)d_in[0];
    float4* out = (float4*)d_out;

    // 16 input floats per thread -> threads = n / 16.
    int total_threads = in_sizes[0] / 16;

    int threads = 512;
    int blocks = (total_threads + threads - 1) / threads;
    haar_kernel<<<blocks, threads>>>(x, out, total_threads);
}